// round 2
// baseline (speedup 1.0000x reference)
#include <cuda_runtime.h>

#define BB   16
#define NN   1024
#define INF  256
#define HH   4
#define DD   64
#define CC   256      // HH*DD
#define NEG_SLOPE 0.2f

// ---- scratch (device globals: no allocation allowed) ----
__device__ float g_h[BB * NN * CC];        // 16 MB: h = x @ W
__device__ float g_ssrc[BB * NN * HH];
__device__ float g_sdst[BB * NN * HH];
__device__ float g_mx[BB * HH];            // max_j s_dst per (b,h)

// ---- f32x2 packed helpers (sm_103a FFMA2) ----
__device__ __forceinline__ unsigned long long pack2(float w) {
    unsigned long long r;
    asm("mov.b64 %0, {%1, %1};" : "=l"(r) : "f"(w));
    return r;
}
__device__ __forceinline__ void fma2(unsigned long long& acc, unsigned long long a, unsigned long long b) {
    asm("fma.rn.f32x2 %0, %1, %2, %0;" : "+l"(acc) : "l"(a), "l"(b));
}
__device__ __forceinline__ float2 unpack2(unsigned long long v) {
    float2 f;
    asm("mov.b64 {%0, %1}, %2;" : "=f"(f.x), "=f"(f.y) : "l"(v));
    return f;
}

// ============================================================
// 1) h = x @ W : [16384,256] @ [256,256], 64x64 tiles, 4x4 micro
// ============================================================
__global__ __launch_bounds__(256) void gemm_kernel(const float* __restrict__ A,
                                                   const float* __restrict__ Bm)
{
    __shared__ float Ast[32][65];   // transposed A tile, pad 65 -> conflict-free
    __shared__ float Bs[32][64];

    int t  = threadIdx.x;
    int ty = t >> 4, tx = t & 15;
    int rowBase = blockIdx.y << 6;
    int colBase = blockIdx.x << 6;

    float acc[4][4] = {};

    for (int k0 = 0; k0 < 256; k0 += 32) {
        #pragma unroll
        for (int l = 0; l < 8; ++l) {
            int idx = t + (l << 8);
            int ar = idx >> 5, ak = idx & 31;
            Ast[ak][ar] = A[(rowBase + ar) * 256 + k0 + ak];
        }
        #pragma unroll
        for (int l = 0; l < 8; ++l) {
            int idx = t + (l << 8);
            int bk = idx >> 6, bc = idx & 63;
            Bs[bk][bc] = Bm[(k0 + bk) * 256 + colBase + bc];
        }
        __syncthreads();
        #pragma unroll
        for (int kk = 0; kk < 32; ++kk) {
            float4 bv = *(const float4*)&Bs[kk][tx << 2];
            float av[4];
            #pragma unroll
            for (int r = 0; r < 4; ++r) av[r] = Ast[kk][(ty << 2) + r];
            #pragma unroll
            for (int r = 0; r < 4; ++r) {
                acc[r][0] += av[r] * bv.x;
                acc[r][1] += av[r] * bv.y;
                acc[r][2] += av[r] * bv.z;
                acc[r][3] += av[r] * bv.w;
            }
        }
        __syncthreads();
    }
    #pragma unroll
    for (int r = 0; r < 4; ++r) {
        float4 o = make_float4(acc[r][0], acc[r][1], acc[r][2], acc[r][3]);
        *(float4*)&g_h[(rowBase + (ty << 2) + r) * 256 + colBase + (tx << 2)] = o;
    }
}

// ============================================================
// 2) s_src[b,n,h] = h[b,n,h,:] . a_src[:,h];  s_dst likewise
// ============================================================
__global__ __launch_bounds__(256) void score_kernel(const float* __restrict__ a)
{
    int bn = blockIdx.x;
    int c  = threadIdx.x;
    float hv = g_h[bn * 256 + c];
    int hd = c >> 6, d = c & 63;
    float ps = hv * a[d * 4 + hd];          // a_src
    float pd = hv * a[(64 + d) * 4 + hd];   // a_dst
    #pragma unroll
    for (int o = 16; o; o >>= 1) {
        ps += __shfl_xor_sync(0xffffffffu, ps, o);
        pd += __shfl_xor_sync(0xffffffffu, pd, o);
    }
    __shared__ float rs[8], rd[8];
    if ((c & 31) == 0) { rs[c >> 5] = ps; rd[c >> 5] = pd; }
    __syncthreads();
    if (c < 4) {
        g_ssrc[bn * 4 + c] = rs[2 * c] + rs[2 * c + 1];
        g_sdst[bn * 4 + c] = rd[2 * c] + rd[2 * c + 1];
    }
}

// ============================================================
// 3) g_mx[b,h] = max_n s_dst[b,n,h]   (valid softmax shift)
// ============================================================
__global__ __launch_bounds__(256) void max_kernel()
{
    int bh = blockIdx.x;
    int b = bh >> 2, h = bh & 3;
    int t = threadIdx.x;
    float m = -3.4e38f;
    for (int n = t; n < NN; n += 256)
        m = fmaxf(m, g_sdst[((b << 10) + n) * 4 + h]);
    #pragma unroll
    for (int o = 16; o; o >>= 1) m = fmaxf(m, __shfl_xor_sync(0xffffffffu, m, o));
    __shared__ float sm_[8];
    if ((t & 31) == 0) sm_[t >> 5] = m;
    __syncthreads();
    if (t == 0) {
        float mm = sm_[0];
        #pragma unroll
        for (int i = 1; i < 8; ++i) mm = fmaxf(mm, sm_[i]);
        g_mx[bh] = mm;
    }
}

// ============================================================
// 4) attention aggregation, 32-row i-tiles x 32-col j-tiles
//    dynamic smem: ws[4][32][32] floats (16KB) + hs[32][256] (32KB) = 48KB
//    (+1.5KB static -> needs MaxDynamicSharedMemorySize opt-in)
// ============================================================
__global__ __launch_bounds__(256) void attn_kernel(const int* __restrict__ adj,
                                                   float* __restrict__ out)
{
    extern __shared__ __align__(16) float dynsm[];
    float* ws = dynsm;            // [h][i][jj] : h*1024 + i*32 + jj
    float* hs = dynsm + 4096;     // [jj][c]    : jj*256 + c

    __shared__ float ssrc_s[32][4], Ms_s[32][4], den_s[32][4];

    int b  = blockIdx.x >> 5;
    int i0 = (blockIdx.x & 31) << 5;
    int t  = threadIdx.x;
    int lane = t & 31, wid = t >> 5;
    int hcol = lane >> 3;                 // head of this thread's output cols

    if (t < 128) {
        int i = t >> 2, h = t & 3;
        float ss = g_ssrc[((b << 10) + i0 + i) * 4 + h];
        ssrc_s[i][h] = ss;
        float m = ss + g_mx[(b << 2) + h];
        Ms_s[i][h] = (m > 0.f) ? m : NEG_SLOPE * m;   // lrelu(ssrc + max sdst) >= all logits
    }

    unsigned long long acc[4][4];
    #pragma unroll
    for (int r = 0; r < 4; ++r)
        #pragma unroll
        for (int k = 0; k < 4; ++k) acc[r][k] = 0ull;
    float dloc[4][4] = {};

    const float4* h4  = (const float4*)g_h;
    const float4* sd4 = (const float4*)g_sdst;
    const ulonglong2* hpo = (const ulonglong2*)hs + (lane << 1);

    for (int jt = 0; jt < 32; ++jt) {
        int j0 = jt << 5;
        __syncthreads();   // previous FMA phase done before overwriting smem

        // -- load h tile: 32 rows x 256 cols
        #pragma unroll
        for (int l = 0; l < 8; ++l) {
            int idx = t + (l << 8);
            ((float4*)hs)[idx] = h4[(((b << 10) + j0) << 6) + idx];
        }

        // -- compute weight tile (coalesced adj reads: lane == j)
        float4 sd = sd4[(b << 10) + j0 + lane];
        #pragma unroll
        for (int r = 0; r < 4; ++r) {
            int i = (wid << 2) + r;
            int av = adj[(((b << 10) + i0 + i) << 10) + j0 + lane];
            float w0 = 0.f, w1 = 0.f, w2 = 0.f, w3 = 0.f;
            if (av > 0) {
                float e0 = ssrc_s[i][0] + sd.x; e0 = (e0 > 0.f) ? e0 : NEG_SLOPE * e0;
                float e1 = ssrc_s[i][1] + sd.y; e1 = (e1 > 0.f) ? e1 : NEG_SLOPE * e1;
                float e2 = ssrc_s[i][2] + sd.z; e2 = (e2 > 0.f) ? e2 : NEG_SLOPE * e2;
                float e3 = ssrc_s[i][3] + sd.w; e3 = (e3 > 0.f) ? e3 : NEG_SLOPE * e3;
                w0 = __expf(e0 - Ms_s[i][0]);
                w1 = __expf(e1 - Ms_s[i][1]);
                w2 = __expf(e2 - Ms_s[i][2]);
                w3 = __expf(e3 - Ms_s[i][3]);
            }
            dloc[r][0] += w0; dloc[r][1] += w1; dloc[r][2] += w2; dloc[r][3] += w3;
            int base = (i << 5) + lane;
            ws[base]        = w0;
            ws[1024 + base] = w1;
            ws[2048 + base] = w2;
            ws[3072 + base] = w3;
        }
        __syncthreads();

        // -- FMA phase: thread = 4 i-rows x 8 cols, packed f32x2
        int wbase = (hcol << 10) + (wid << 7);   // h*1024 + (wid*4)*32
        #pragma unroll 4
        for (int jj = 0; jj < 32; ++jj) {
            ulonglong2 p0 = hpo[jj << 6];
            ulonglong2 p1 = hpo[(jj << 6) + 1];
            #pragma unroll
            for (int r = 0; r < 4; ++r) {
                unsigned long long w2p = pack2(ws[wbase + (r << 5) + jj]);
                fma2(acc[r][0], w2p, p0.x);
                fma2(acc[r][1], w2p, p0.y);
                fma2(acc[r][2], w2p, p1.x);
                fma2(acc[r][3], w2p, p1.y);
            }
        }
    }

    // -- denominator: reduce dloc over the 32 j-lanes of each warp
    #pragma unroll
    for (int r = 0; r < 4; ++r)
        #pragma unroll
        for (int h = 0; h < 4; ++h) {
            float v = dloc[r][h];
            #pragma unroll
            for (int o = 16; o; o >>= 1) v += __shfl_xor_sync(0xffffffffu, v, o);
            if (lane == 0) den_s[(wid << 2) + r][h] = v;
        }
    __syncthreads();

    // -- normalize + store
    #pragma unroll
    for (int r = 0; r < 4; ++r) {
        int i = (wid << 2) + r;
        float dinv = 1.f / den_s[i][hcol];
        float2 f0 = unpack2(acc[r][0]);
        float2 f1 = unpack2(acc[r][1]);
        float2 f2 = unpack2(acc[r][2]);
        float2 f3 = unpack2(acc[r][3]);
        float4 o0 = make_float4(f0.x * dinv, f0.y * dinv, f1.x * dinv, f1.y * dinv);
        float4 o1 = make_float4(f2.x * dinv, f2.y * dinv, f3.x * dinv, f3.y * dinv);
        float4* op = (float4*)out + ((((b << 10) + i0 + i) << 6) + (lane << 1));
        op[0] = o0;
        op[1] = o1;
    }
}

// ============================================================
extern "C" void kernel_launch(void* const* d_in, const int* in_sizes, int n_in,
                              void* d_out, int out_size)
{
    // Opt in to >48KB (dynamic+static) shared for attn_kernel.
    // Host-side, non-stream API: legal during graph capture, never replayed.
    cudaFuncSetAttribute(attn_kernel, cudaFuncAttributeMaxDynamicSharedMemorySize, 65536);

    // size-based input detection (all element counts distinct)
    const float* x = nullptr; const int* adj = nullptr;
    const float* W = nullptr; const float* a = nullptr;
    for (int i = 0; i < n_in; ++i) {
        int s = in_sizes[i];
        if      (s == BB * NN * INF) x   = (const float*)d_in[i];
        else if (s == BB * NN * NN)  adj = (const int*)d_in[i];
        else if (s == INF * HH * DD) W   = (const float*)d_in[i];
        else if (s == 2 * DD * HH)   a   = (const float*)d_in[i];
    }

    gemm_kernel<<<dim3(4, 256), 256>>>(x, W);
    score_kernel<<<BB * NN, 256>>>(a);
    max_kernel<<<BB * HH, 256>>>();
    attn_kernel<<<BB * (NN / 32), 256, 49152>>>(adj, (float*)d_out);
}

// round 3
// speedup vs baseline: 1.3659x; 1.3659x over previous
#include <cuda_runtime.h>

#define BB   16
#define NN   1024
#define INF  256
#define HH   4
#define DD   64
#define CC   256      // HH*DD
#define NEG_SLOPE 0.2f

// ---- scratch (device globals: no allocation allowed) ----
__device__ float g_h[BB * NN * CC];        // 16 MB: h = x @ W
__device__ float g_ssrc[BB * NN * HH];
__device__ float g_sdst[BB * NN * HH];
__device__ float g_mx[BB * HH];            // max_j s_dst per (b,h)

// ---- f32x2 packed helpers (sm_103a FFMA2) ----
__device__ __forceinline__ unsigned long long pack2(float w) {
    unsigned long long r;
    asm("mov.b64 %0, {%1, %1};" : "=l"(r) : "f"(w));
    return r;
}
__device__ __forceinline__ unsigned long long packpair(float a, float b) {
    unsigned long long r;
    asm("mov.b64 %0, {%1, %2};" : "=l"(r) : "f"(a), "f"(b));
    return r;
}
__device__ __forceinline__ void fma2(unsigned long long& acc, unsigned long long a, unsigned long long b) {
    asm("fma.rn.f32x2 %0, %1, %2, %0;" : "+l"(acc) : "l"(a), "l"(b));
}
__device__ __forceinline__ void fadd2(unsigned long long& acc, unsigned long long a) {
    asm("add.rn.f32x2 %0, %0, %1;" : "+l"(acc) : "l"(a));
}
__device__ __forceinline__ float2 unpack2(unsigned long long v) {
    float2 f;
    asm("mov.b64 {%0, %1}, %2;" : "=f"(f.x), "=f"(f.y) : "l"(v));
    return f;
}

// ============================================================
// 1) h = x @ W : [16384,256] @ [256,256], 64x64 tiles, 4x4 micro
// ============================================================
__global__ __launch_bounds__(256) void gemm_kernel(const float* __restrict__ A,
                                                   const float* __restrict__ Bm)
{
    __shared__ float Ast[32][65];
    __shared__ float Bs[32][64];

    int t  = threadIdx.x;
    int ty = t >> 4, tx = t & 15;
    int rowBase = blockIdx.y << 6;
    int colBase = blockIdx.x << 6;

    float acc[4][4] = {};

    for (int k0 = 0; k0 < 256; k0 += 32) {
        #pragma unroll
        for (int l = 0; l < 8; ++l) {
            int idx = t + (l << 8);
            int ar = idx >> 5, ak = idx & 31;
            Ast[ak][ar] = A[(rowBase + ar) * 256 + k0 + ak];
        }
        #pragma unroll
        for (int l = 0; l < 8; ++l) {
            int idx = t + (l << 8);
            int bk = idx >> 6, bc = idx & 63;
            Bs[bk][bc] = Bm[(k0 + bk) * 256 + colBase + bc];
        }
        __syncthreads();
        #pragma unroll
        for (int kk = 0; kk < 32; ++kk) {
            float4 bv = *(const float4*)&Bs[kk][tx << 2];
            float av[4];
            #pragma unroll
            for (int r = 0; r < 4; ++r) av[r] = Ast[kk][(ty << 2) + r];
            #pragma unroll
            for (int r = 0; r < 4; ++r) {
                acc[r][0] += av[r] * bv.x;
                acc[r][1] += av[r] * bv.y;
                acc[r][2] += av[r] * bv.z;
                acc[r][3] += av[r] * bv.w;
            }
        }
        __syncthreads();
    }
    #pragma unroll
    for (int r = 0; r < 4; ++r) {
        float4 o = make_float4(acc[r][0], acc[r][1], acc[r][2], acc[r][3]);
        *(float4*)&g_h[(rowBase + (ty << 2) + r) * 256 + colBase + (tx << 2)] = o;
    }
}

// ============================================================
// 2) s_src[b,n,h] = h[b,n,h,:] . a_src[:,h];  s_dst likewise
// ============================================================
__global__ __launch_bounds__(256) void score_kernel(const float* __restrict__ a)
{
    int bn = blockIdx.x;
    int c  = threadIdx.x;
    float hv = g_h[bn * 256 + c];
    int hd = c >> 6, d = c & 63;
    float ps = hv * a[d * 4 + hd];
    float pd = hv * a[(64 + d) * 4 + hd];
    #pragma unroll
    for (int o = 16; o; o >>= 1) {
        ps += __shfl_xor_sync(0xffffffffu, ps, o);
        pd += __shfl_xor_sync(0xffffffffu, pd, o);
    }
    __shared__ float rs[8], rd[8];
    if ((c & 31) == 0) { rs[c >> 5] = ps; rd[c >> 5] = pd; }
    __syncthreads();
    if (c < 4) {
        g_ssrc[bn * 4 + c] = rs[2 * c] + rs[2 * c + 1];
        g_sdst[bn * 4 + c] = rd[2 * c] + rd[2 * c + 1];
    }
}

// ============================================================
// 3) g_mx[b,h] = max_n s_dst[b,n,h]   (valid softmax shift)
// ============================================================
__global__ __launch_bounds__(256) void max_kernel()
{
    int bh = blockIdx.x;
    int b = bh >> 2, h = bh & 3;
    int t = threadIdx.x;
    float m = -3.4e38f;
    for (int n = t; n < NN; n += 256)
        m = fmaxf(m, g_sdst[((b << 10) + n) * 4 + h]);
    #pragma unroll
    for (int o = 16; o; o >>= 1) m = fmaxf(m, __shfl_xor_sync(0xffffffffu, m, o));
    __shared__ float sm_[8];
    if ((t & 31) == 0) sm_[t >> 5] = m;
    __syncthreads();
    if (t == 0) {
        float mm = sm_[0];
        #pragma unroll
        for (int i = 1; i < 8; ++i) mm = fmaxf(mm, sm_[i]);
        g_mx[bh] = mm;
    }
}

// ============================================================
// 4) attention aggregation v2:
//    CTA = 128 threads (4 warps), i-tile = 32, j-tile = 32.
//    Warp w owns 8 i-rows; lane owns 8 cols (head = lane>>3).
//    Thread tile 8x8 -> 32 fma2/jj, smem bytes/MAC = 0.75.
//    Denominator folded into FMA phase (4 fadd2/jj), no reduce.
//    dyn smem: ws[4][32][32] (16KB) + hs[32][256] (32KB) = 48KB
// ============================================================
__global__ __launch_bounds__(128, 4) void attn_kernel(const int* __restrict__ adj,
                                                      float* __restrict__ out)
{
    extern __shared__ __align__(16) float dynsm[];
    float* ws = dynsm;            // [h][i][j] : h*1024 + i*32 + j
    float* hs = dynsm + 4096;     // [jj][c]   : jj*256 + c

    __shared__ float ssrc_s[32][4], Ms_s[32][4];

    int b  = blockIdx.x >> 5;
    int i0 = (blockIdx.x & 31) << 5;
    int t  = threadIdx.x;
    int lane = t & 31, wid = t >> 5;        // wid in 0..3
    int hcol = lane >> 3;                   // head of this thread's 8 output cols

    {   // 128 threads cover 32 rows x 4 heads
        int i = t >> 2, h = t & 3;
        float ss = g_ssrc[((b << 10) + i0 + i) * 4 + h];
        ssrc_s[i][h] = ss;
        float m = ss + g_mx[(b << 2) + h];
        Ms_s[i][h] = (m > 0.f) ? m : NEG_SLOPE * m;   // >= all logits of row i, head h
    }

    unsigned long long acc[8][4];
    #pragma unroll
    for (int r = 0; r < 8; ++r)
        #pragma unroll
        for (int k = 0; k < 4; ++k) acc[r][k] = 0ull;
    unsigned long long den2[4] = {0ull, 0ull, 0ull, 0ull};   // (w0,w1)(w2,w3)(w4,w5)(w6,w7) sums

    const float4* h4  = (const float4*)g_h;
    const float4* sd4 = (const float4*)g_sdst;
    const ulonglong2* hpo = (const ulonglong2*)hs + (lane << 1);
    const int wsbase = (hcol << 10) + (wid << 8);   // h*1024 + (wid*8)*32

    for (int jt = 0; jt < 32; ++jt) {
        int j0 = jt << 5;
        __syncthreads();   // previous FMA phase done before overwriting smem

        // -- load h tile: 32 rows x 256 cols = 2048 float4, 16 per thread
        {
            int gbase = ((b << 10) + j0) << 6;
            #pragma unroll
            for (int l = 0; l < 16; ++l) {
                int idx = t + (l << 7);
                ((float4*)hs)[idx] = h4[gbase + idx];
            }
        }

        // -- weight tile: lane = j (coalesced adj), 8 rows x 4 heads per thread
        float4 sd = sd4[(b << 10) + j0 + lane];
        #pragma unroll
        for (int r = 0; r < 8; ++r) {
            int i = (wid << 3) + r;
            int av = adj[(((b << 10) + i0 + i) << 10) + j0 + lane];
            float w0 = 0.f, w1 = 0.f, w2 = 0.f, w3 = 0.f;
            if (av > 0) {
                float e0 = ssrc_s[i][0] + sd.x; e0 = (e0 > 0.f) ? e0 : NEG_SLOPE * e0;
                float e1 = ssrc_s[i][1] + sd.y; e1 = (e1 > 0.f) ? e1 : NEG_SLOPE * e1;
                float e2 = ssrc_s[i][2] + sd.z; e2 = (e2 > 0.f) ? e2 : NEG_SLOPE * e2;
                float e3 = ssrc_s[i][3] + sd.w; e3 = (e3 > 0.f) ? e3 : NEG_SLOPE * e3;
                w0 = __expf(e0 - Ms_s[i][0]);
                w1 = __expf(e1 - Ms_s[i][1]);
                w2 = __expf(e2 - Ms_s[i][2]);
                w3 = __expf(e3 - Ms_s[i][3]);
            }
            int base = (i << 5) + lane;
            ws[base]        = w0;
            ws[1024 + base] = w1;
            ws[2048 + base] = w2;
            ws[3072 + base] = w3;
        }
        __syncthreads();

        // -- FMA phase: 8 rows x 8 cols per thread, packed f32x2
        #pragma unroll 4
        for (int jj = 0; jj < 32; ++jj) {
            ulonglong2 p0 = hpo[jj << 6];
            ulonglong2 p1 = hpo[(jj << 6) + 1];
            float w[8];
            #pragma unroll
            for (int r = 0; r < 8; ++r)
                w[r] = ws[wsbase + (r << 5) + jj];   // 8-lane broadcast
            #pragma unroll
            for (int q = 0; q < 4; ++q)
                fadd2(den2[q], packpair(w[2 * q], w[2 * q + 1]));
            #pragma unroll
            for (int r = 0; r < 8; ++r) {
                unsigned long long w2p = pack2(w[r]);
                fma2(acc[r][0], w2p, p0.x);
                fma2(acc[r][1], w2p, p0.y);
                fma2(acc[r][2], w2p, p1.x);
                fma2(acc[r][3], w2p, p1.y);
            }
        }
    }

    // -- normalize + store (den2 holds full denominators for this thread's rows/head)
    float den[8];
    #pragma unroll
    for (int q = 0; q < 4; ++q) {
        float2 d = unpack2(den2[q]);
        den[2 * q] = d.x; den[2 * q + 1] = d.y;
    }
    #pragma unroll
    for (int r = 0; r < 8; ++r) {
        int i = (wid << 3) + r;
        float dinv = 1.f / den[r];
        float2 f0 = unpack2(acc[r][0]);
        float2 f1 = unpack2(acc[r][1]);
        float2 f2 = unpack2(acc[r][2]);
        float2 f3 = unpack2(acc[r][3]);
        float4 o0 = make_float4(f0.x * dinv, f0.y * dinv, f1.x * dinv, f1.y * dinv);
        float4 o1 = make_float4(f2.x * dinv, f2.y * dinv, f3.x * dinv, f3.y * dinv);
        float4* op = (float4*)out + ((((b << 10) + i0 + i) << 6) + (lane << 1));
        op[0] = o0;
        op[1] = o1;
    }
}

// ============================================================
extern "C" void kernel_launch(void* const* d_in, const int* in_sizes, int n_in,
                              void* d_out, int out_size)
{
    cudaFuncSetAttribute(attn_kernel, cudaFuncAttributeMaxDynamicSharedMemorySize, 65536);

    const float* x = nullptr; const int* adj = nullptr;
    const float* W = nullptr; const float* a = nullptr;
    for (int i = 0; i < n_in; ++i) {
        int s = in_sizes[i];
        if      (s == BB * NN * INF) x   = (const float*)d_in[i];
        else if (s == BB * NN * NN)  adj = (const int*)d_in[i];
        else if (s == INF * HH * DD) W   = (const float*)d_in[i];
        else if (s == 2 * DD * HH)   a   = (const float*)d_in[i];
    }

    gemm_kernel<<<dim3(4, 256), 256>>>(x, W);
    score_kernel<<<BB * NN, 256>>>(a);
    max_kernel<<<BB * HH, 256>>>();
    attn_kernel<<<BB * (NN / 32), 128, 49152>>>(adj, (float*)d_out);
}